// round 16
// baseline (speedup 1.0000x reference)
#include <cuda_runtime.h>
#include <cuda_bf16.h>
#include <cstdint>

#define PROMPT_LEN 2048
#define VOCAB 49408
#define DIM 768

#define BM 128
#define BN 128
#define BK 64                   // bf16 elems per chunk = 128 B per row
#define NCHUNK (DIM / BK)       // 12
#define STAGES 3
#define ASTAGE_BYTES (BM * 128)                 // 16 KB
#define STAGE_BYTES (2 * ASTAGE_BYTES)          // 32 KB
#define RM_OFF (STAGES * STAGE_BYTES)           // 98304
#define SMEM_TOTAL (RM_OFF + 1024)

#define NVT (VOCAB / BN)        // 386
#define EPS 0.3f
#define STAGE_CAP 4096u
#define CAND_CAP (2u * 1024u * 1024u)

#define CLIP_BLOCKS (VOCAB / 4)       // 12352
#define PROMPT_BLOCKS (PROMPT_LEN / 4)

// ---------------- scratch (chunk-tiled, swizzle baked into global) -------
__device__ uint8_t g_clip_t[(size_t)NCHUNK * VOCAB * 128];       // 76 MB
__device__ uint8_t g_prompt_t[(size_t)NCHUNK * PROMPT_LEN * 128];
__device__ float g_c_sq[VOCAB];
__device__ unsigned g_rowmin[PROMPT_LEN];                        // ordered uint
__device__ unsigned long long g_keys2[PROMPT_LEN];               // (q<<16)|col
__device__ unsigned g_cand_count;
__device__ float4 g_cand[CAND_CAP];                              // {score,row,col,-}

// ---------------- helpers ----------------
__device__ __forceinline__ uint32_t smem_u32(const void* p) {
    uint32_t a;
    asm("{ .reg .u64 t; cvta.to.shared.u64 t, %1; cvt.u32.u64 %0, t; }" : "=r"(a) : "l"(p));
    return a;
}
__device__ __forceinline__ unsigned f2ord(float f) {
    unsigned u = __float_as_uint(f);
    return (u & 0x80000000u) ? ~u : (u | 0x80000000u);
}
__device__ __forceinline__ float ord2f(unsigned k) {
    unsigned u = (k & 0x80000000u) ? (k & 0x7FFFFFFFu) : ~k;
    return __uint_as_float(u);
}
__device__ __forceinline__ void ldsm4(uint32_t* r, uint32_t a) {
    asm volatile("ldmatrix.sync.aligned.m8n8.x4.shared.b16 {%0,%1,%2,%3}, [%4];"
                 : "=r"(r[0]), "=r"(r[1]), "=r"(r[2]), "=r"(r[3]) : "r"(a));
}
__device__ __forceinline__ void mma16816(float* c, const uint32_t* a, uint32_t b0, uint32_t b1) {
    asm volatile(
        "mma.sync.aligned.m16n8k16.row.col.f32.bf16.bf16.f32 "
        "{%0,%1,%2,%3}, {%4,%5,%6,%7}, {%8,%9}, {%0,%1,%2,%3};\n"
        : "+f"(c[0]), "+f"(c[1]), "+f"(c[2]), "+f"(c[3])
        : "r"(a[0]), "r"(a[1]), "r"(a[2]), "r"(a[3]), "r"(b0), "r"(b1));
}
__device__ __forceinline__ void bulk_g2s(uint32_t dst, const void* src, uint32_t bytes,
                                         uint32_t mbar) {
    asm volatile(
        "cp.async.bulk.shared::cta.global.mbarrier::complete_tx::bytes [%0], [%1], %2, [%3];"
        :: "r"(dst), "l"(src), "r"(bytes), "r"(mbar) : "memory");
}
#define MBAR_INIT(a, n) \
    asm volatile("mbarrier.init.shared.b64 [%0], %1;" :: "r"(a), "r"(n) : "memory")
#define MBAR_EXPECT(a, tx) \
    asm volatile("mbarrier.arrive.expect_tx.shared.b64 _, [%0], %1;" :: "r"(a), "r"(tx) : "memory")
#define MBAR_ARRIVE(a) \
    asm volatile("mbarrier.arrive.shared.b64 _, [%0];" :: "r"(a) : "memory")
__device__ __forceinline__ void mbar_wait(uint32_t mbar, uint32_t parity) {
    uint32_t done;
    asm volatile(
        "{\n\t.reg .pred p;\n\t"
        "mbarrier.try_wait.parity.acquire.cta.shared::cta.b64 p, [%1], %2;\n\t"
        "selp.b32 %0, 1, 0, p;\n\t}"
        : "=r"(done) : "r"(mbar), "r"(parity) : "memory");
    if (!done) {
        asm volatile(
            "{\n\t.reg .pred P1;\n\t"
            "WL_%=:\n\t"
            "mbarrier.try_wait.parity.acquire.cta.shared::cta.b64 P1, [%0], %1, 0x989680;\n\t"
            "@P1 bra.uni WD_%=;\n\t"
            "bra.uni WL_%=;\n\t"
            "WD_%=:\n\t}"
            :: "r"(mbar), "r"(parity) : "memory");
    }
}

// ---------------- prep: fused clip+prompt convert + K-tile + swizzle -----
// warp-per-row, 4 rows per 128-thread block; float4 loads; 16B stores.
__global__ void prep_all_kernel(const float* __restrict__ clip,
                                const float* __restrict__ prompt) {
    __shared__ __nv_bfloat16 srow[4][DIM];
    const int lane = threadIdx.x & 31;
    const int w = threadIdx.x >> 5;
    const int isclip = (blockIdx.x < CLIP_BLOCKS);
    const int b = isclip ? blockIdx.x : blockIdx.x - CLIP_BLOCKS;
    const int r = b * 4 + w;
    const float* row = (isclip ? clip : prompt) + (size_t)r * DIM;

    float ss = 0.f;
    #pragma unroll
    for (int i = 0; i < 6; i++) {             // 6 float4 per lane = 24 elems
        int f4 = lane + i * 32;               // 192 float4 = 768 floats
        float4 x = *(const float4*)&row[f4 * 4];
        ss += x.x * x.x + x.y * x.y + x.z * x.z + x.w * x.w;
        __nv_bfloat16* d = &srow[w][f4 * 4];
        d[0] = __float2bfloat16(x.x);
        d[1] = __float2bfloat16(x.y);
        d[2] = __float2bfloat16(x.z);
        d[3] = __float2bfloat16(x.w);
    }
    if (isclip) {
        #pragma unroll
        for (int off = 16; off > 0; off >>= 1)
            ss += __shfl_xor_sync(0xffffffffu, ss, off);
        if (lane == 0) g_c_sq[r] = ss;
    }
    __syncwarp();
    uint8_t* gbase = isclip ? g_clip_t : g_prompt_t;
    const size_t nrows = isclip ? VOCAB : PROMPT_LEN;
    #pragma unroll
    for (int t = 0; t < 3; t++) {             // 96 segs of 16B per row
        int seg = lane + t * 32;
        int c = seg >> 3, k = seg & 7;
        uint4 val = *(const uint4*)&srow[w][c * 64 + k * 8];
        uint8_t* dst = gbase + ((size_t)c * nrows + r) * 128
                     + ((k * 16) ^ ((r & 7) << 4));
        *(uint4*)dst = val;
    }
    if (!isclip && lane == 0) {
        g_keys2[r] = 0xFFFFFFFFFFFFFFFFull;
        g_rowmin[r] = 0xFFFFFFFFu;
        if (r == 0) g_cand_count = 0u;
    }
}

// ---------------- Pass A: skew-pipelined bf16 GEMM + candidates ---------
__global__ void __launch_bounds__(256, 2)
nn_kernel() {
    extern __shared__ __align__(1024) char smem[];
    const uint32_t sb = smem_u32(smem);
    const int tid = threadIdx.x;
    const int wid = tid >> 5, lane = tid & 31;
    const int wm = wid & 1, wn = wid >> 1;
    const int g = lane >> 2, tid4 = lane & 3;
    const int j = lane & 7, sel = lane >> 3;
    const int p0 = blockIdx.x * BM;
    const int v0 = blockIdx.y * BN;
    const uint32_t mb_full  = sb + RM_OFF + 640;   // 3 x 8B
    const uint32_t mb_empty = sb + RM_OFF + 672;   // 3 x 8B

    if (tid == 0) {
        #pragma unroll
        for (int s = 0; s < 3; s++) {
            MBAR_INIT(mb_full + s * 8, 1u);
            MBAR_INIT(mb_empty + s * 8, 256u);
        }
    }
    __syncthreads();

    auto issue = [&](int c) {
        int s = c % 3;
        uint32_t stage = sb + s * STAGE_BYTES;
        MBAR_EXPECT(mb_full + s * 8, (uint32_t)STAGE_BYTES);
        bulk_g2s(stage, g_prompt_t + ((size_t)c * PROMPT_LEN + p0) * 128,
                 ASTAGE_BYTES, mb_full + s * 8);
        bulk_g2s(stage + ASTAGE_BYTES, g_clip_t + ((size_t)c * VOCAB + v0) * 128,
                 ASTAGE_BYTES, mb_full + s * 8);
    };

    if (tid == 0) { issue(0); issue(1); issue(2); }

    float acc[4][4][4];
    #pragma unroll
    for (int m = 0; m < 4; m++)
        #pragma unroll
        for (int n = 0; n < 4; n++)
            #pragma unroll
            for (int q = 0; q < 4; q++) acc[m][n][q] = 0.f;

    const uint32_t a_row = (uint32_t)(j + 8 * (sel & 1)) * 128u;
    const uint32_t b_row = (uint32_t)(j + 8 * (sel >> 1)) * 128u;
    const uint32_t a_c16 = 16u * (uint32_t)(sel >> 1);
    const uint32_t b_c16 = 16u * (uint32_t)(sel & 1);
    const uint32_t xorm = (uint32_t)j << 4;

    for (int c = 0; c < NCHUNK; c++) {
        const int s = c % 3;

        mbar_wait(mb_full + s * 8, (uint32_t)((c / 3) & 1));

        const uint32_t stA = sb + (uint32_t)s * STAGE_BYTES;
        const uint32_t stB = stA + ASTAGE_BYTES;
        #pragma unroll
        for (int ks = 0; ks < 4; ks++) {       // 4 x k16 = 64 bf16 = 32B steps
            const uint32_t KB = (uint32_t)ks * 32u;
            uint32_t a[4][4], b[2][4];
            #pragma unroll
            for (int mf = 0; mf < 4; mf++) {
                uint32_t addr = stA + (uint32_t)(wm * 64 + mf * 16) * 128u + a_row
                              + ((KB + a_c16) ^ xorm);
                ldsm4(a[mf], addr);
            }
            #pragma unroll
            for (int nf2 = 0; nf2 < 2; nf2++) {
                uint32_t addr = stB + (uint32_t)(wn * 32 + nf2 * 16) * 128u + b_row
                              + ((KB + b_c16) ^ xorm);
                ldsm4(b[nf2], addr);
            }
            #pragma unroll
            for (int mf = 0; mf < 4; mf++)
                #pragma unroll
                for (int nf = 0; nf < 4; nf++)
                    mma16816(acc[mf][nf], a[mf], b[nf >> 1][2 * (nf & 1)],
                             b[nf >> 1][2 * (nf & 1) + 1]);
        }
        // this thread is done reading stage s for round c/3
        MBAR_ARRIVE(mb_empty + s * 8);

        // producer refills AFTER its own arrive (R11 deadlock lesson)
        if (tid == 0 && c + 3 < NCHUNK) {
            mbar_wait(mb_empty + s * 8, (uint32_t)((c / 3) & 1));
            issue(c + 3);
        }
    }

    // ---------------- epilogue ----------------
    unsigned* rowmin = (unsigned*)(smem + RM_OFF);
    unsigned* s_cnt  = (unsigned*)(smem + RM_OFF + 512);
    unsigned* s_base = (unsigned*)(smem + RM_OFF + 516);
    float4* staging  = (float4*)smem;

    if (tid < BM) rowmin[tid] = 0xFFFFFFFFu;
    if (tid == 0) *s_cnt = 0u;
    __syncthreads();     // all warps out of mainloop; staging smem free

    float cs[8];
    #pragma unroll
    for (int nf = 0; nf < 4; nf++)
        #pragma unroll
        for (int jj = 0; jj < 2; jj++)
            cs[nf * 2 + jj] = __ldg(&g_c_sq[v0 + wn * 32 + nf * 8 + 2 * tid4 + jj]);

    // CTA per-row min (quad-reduced)
    #pragma unroll
    for (int mf = 0; mf < 4; mf++)
        #pragma unroll
        for (int h = 0; h < 2; h++) {
            int lr = wm * 64 + mf * 16 + h * 8 + g;
            float best = 3.4e38f;
            #pragma unroll
            for (int nf = 0; nf < 4; nf++)
                #pragma unroll
                for (int jj = 0; jj < 2; jj++) {
                    float s = cs[nf * 2 + jj] - 2.0f * acc[mf][nf][h * 2 + jj];
                    best = fminf(best, s);
                }
            #pragma unroll
            for (int off = 1; off < 4; off <<= 1)
                best = fminf(best, __shfl_xor_sync(0xffffffffu, best, off));
            if (tid4 == 0) atomicMin(&rowmin[lr], f2ord(best));
        }
    __syncthreads();

    // global row-min directly (replaces g_ctamin + reduce kernel)
    if (tid < BM) atomicMin(&g_rowmin[p0 + tid], rowmin[tid]);

    // warp-aggregated candidate push
    #pragma unroll
    for (int mf = 0; mf < 4; mf++)
        #pragma unroll
        for (int h = 0; h < 2; h++) {
            int lr = wm * 64 + mf * 16 + h * 8 + g;
            float thr = ord2f(rowmin[lr]) + EPS;
            #pragma unroll
            for (int nf = 0; nf < 4; nf++)
                #pragma unroll
                for (int jj = 0; jj < 2; jj++) {
                    float s = cs[nf * 2 + jj] - 2.0f * acc[mf][nf][h * 2 + jj];
                    bool pred = (s <= thr);
                    unsigned mask = __ballot_sync(0xffffffffu, pred);
                    if (mask) {
                        int leader = __ffs(mask) - 1;
                        unsigned base = 0;
                        if (lane == leader)
                            base = atomicAdd(s_cnt, (unsigned)__popc(mask));
                        base = __shfl_sync(0xffffffffu, base, leader);
                        if (pred) {
                            unsigned slot = base + __popc(mask & ((1u << lane) - 1u));
                            float4 val = make_float4(
                                s, __uint_as_float((unsigned)(p0 + lr)),
                                __uint_as_float((unsigned)(v0 + wn * 32 + nf * 8 + 2 * tid4 + jj)),
                                0.f);
                            if (slot < STAGE_CAP) staging[slot] = val;
                            else {
                                unsigned gs = atomicAdd(&g_cand_count, 1u);
                                if (gs < CAND_CAP) g_cand[gs] = val;
                            }
                        }
                    }
                }
        }
    __syncthreads();
    unsigned cnt = min(*s_cnt, STAGE_CAP);
    if (tid == 0) *s_base = atomicAdd(&g_cand_count, cnt);
    __syncthreads();
    unsigned base = *s_base;
    for (unsigned i = tid; i < cnt; i += 256)
        if (base + i < CAND_CAP) g_cand[base + i] = staging[i];
}

// ---------------- Pass B: exact rescore ----------------
__global__ void rescore_kernel(const float* __restrict__ prompt,
                               const float* __restrict__ clip) {
    unsigned n = g_cand_count;
    if (n > CAND_CAP) n = CAND_CAP;
    int lane = threadIdx.x & 31;
    unsigned gw = (blockIdx.x * blockDim.x + threadIdx.x) >> 5;
    unsigned nw = (gridDim.x * blockDim.x) >> 5;
    for (unsigned i = gw; i < n; i += nw) {
        float4 cand = g_cand[i];
        float s = cand.x;
        unsigned row = __float_as_uint(cand.y);
        unsigned col = __float_as_uint(cand.z);
        float minf = ord2f(g_rowmin[row]);
        if (s <= minf + EPS) {
            const float* p = prompt + (size_t)row * DIM;
            const float* c = clip + (size_t)col * DIM;
            double d2 = 0.0;
            for (int k = lane; k < DIM; k += 32) {
                double d = (double)p[k] - (double)c[k];
                d2 += d * d;
            }
            #pragma unroll
            for (int off = 16; off > 0; off >>= 1)
                d2 += __shfl_xor_sync(0xffffffffu, d2, off);
            if (lane == 0) {
                unsigned long long q = (unsigned long long)llround(d2 * 1048576.0);
                atomicMin(&g_keys2[row], (q << 16) | (unsigned long long)col);
            }
        }
    }
}

// ---------------- gather ----------------
__global__ void gather_kernel(const float* __restrict__ clip,
                              float* __restrict__ out, int write_ids) {
    int p = blockIdx.x;
    unsigned idx = (unsigned)(g_keys2[p] & 0xFFFFull);
    const float* src = clip + (size_t)idx * DIM;
    float* dst = out + (size_t)p * DIM;
    for (int i = threadIdx.x; i < DIM; i += blockDim.x) dst[i] = src[i];
    if (threadIdx.x == 0 && write_ids)
        out[(size_t)PROMPT_LEN * DIM + p] = (float)idx;
}

// ---------------- launch ----------------
extern "C" void kernel_launch(void* const* d_in, const int* in_sizes, int n_in,
                              void* d_out, int out_size) {
    const float* prompt = (const float*)d_in[0];   // (2048, 768) fp32
    const float* clip   = (const float*)d_in[1];   // (49408, 768) fp32
    float* out = (float*)d_out;

    cudaFuncSetAttribute(nn_kernel, cudaFuncAttributeMaxDynamicSharedMemorySize,
                         SMEM_TOTAL);

    prep_all_kernel<<<CLIP_BLOCKS + PROMPT_BLOCKS, 128>>>(clip, prompt);

    dim3 grid(PROMPT_LEN / BM, NVT);   // (16, 386); x fast -> clip tile reuse in L2
    nn_kernel<<<grid, 256, SMEM_TOTAL>>>();

    rescore_kernel<<<256, 256>>>(prompt, clip);

    int write_ids = (out_size >= PROMPT_LEN * DIM + PROMPT_LEN) ? 1 : 0;
    gather_kernel<<<PROMPT_LEN, 128>>>(clip, out, write_ids);
}

// round 17
// speedup vs baseline: 1.3317x; 1.3317x over previous
#include <cuda_runtime.h>
#include <cuda_bf16.h>
#include <cstdint>

#define PROMPT_LEN 2048
#define VOCAB 49408
#define DIM 768

#define BM 128
#define BN 128
#define BK 64                   // bf16 elems per chunk = 128 B per row
#define NCHUNK (DIM / BK)       // 12
#define STAGES 3
#define ASTAGE_BYTES (BM * 128)                 // 16 KB
#define STAGE_BYTES (2 * ASTAGE_BYTES)          // 32 KB
#define RM_OFF (STAGES * STAGE_BYTES)           // 98304
#define SMEM_TOTAL (RM_OFF + 2048)

#define NVT (VOCAB / BN)        // 386
#define EPS 0.3f
#define STAGE_CAP 4096u
#define CAND_CAP (2u * 1024u * 1024u)

// ---------------- scratch (chunk-tiled, swizzle baked into global) -------
__device__ uint8_t g_clip_t[(size_t)NCHUNK * VOCAB * 128];       // 76 MB
__device__ uint8_t g_prompt_t[(size_t)NCHUNK * PROMPT_LEN * 128];
__device__ float g_c_sq[VOCAB];
__device__ unsigned g_ctamin[(size_t)NVT * PROMPT_LEN];
__device__ unsigned g_rowmin[PROMPT_LEN];                        // ordered uint
__device__ unsigned long long g_keys2[PROMPT_LEN];               // (q<<16)|col
__device__ unsigned g_cand_count;
__device__ float4 g_cand[CAND_CAP];                              // {score,row,col,-}

// ---------------- helpers ----------------
__device__ __forceinline__ uint32_t smem_u32(const void* p) {
    uint32_t a;
    asm("{ .reg .u64 t; cvta.to.shared.u64 t, %1; cvt.u32.u64 %0, t; }" : "=r"(a) : "l"(p));
    return a;
}
__device__ __forceinline__ unsigned f2ord(float f) {
    unsigned u = __float_as_uint(f);
    return (u & 0x80000000u) ? ~u : (u | 0x80000000u);
}
__device__ __forceinline__ float ord2f(unsigned k) {
    unsigned u = (k & 0x80000000u) ? (k & 0x7FFFFFFFu) : ~k;
    return __uint_as_float(u);
}
__device__ __forceinline__ void ldsm4(uint32_t* r, uint32_t a) {
    asm volatile("ldmatrix.sync.aligned.m8n8.x4.shared.b16 {%0,%1,%2,%3}, [%4];"
                 : "=r"(r[0]), "=r"(r[1]), "=r"(r[2]), "=r"(r[3]) : "r"(a));
}
__device__ __forceinline__ void mma16816(float* c, const uint32_t* a, uint32_t b0, uint32_t b1) {
    asm volatile(
        "mma.sync.aligned.m16n8k16.row.col.f32.bf16.bf16.f32 "
        "{%0,%1,%2,%3}, {%4,%5,%6,%7}, {%8,%9}, {%0,%1,%2,%3};\n"
        : "+f"(c[0]), "+f"(c[1]), "+f"(c[2]), "+f"(c[3])
        : "r"(a[0]), "r"(a[1]), "r"(a[2]), "r"(a[3]), "r"(b0), "r"(b1));
}
__device__ __forceinline__ void bulk_g2s(uint32_t dst, const void* src, uint32_t bytes,
                                         uint32_t mbar) {
    asm volatile(
        "cp.async.bulk.shared::cta.global.mbarrier::complete_tx::bytes [%0], [%1], %2, [%3];"
        :: "r"(dst), "l"(src), "r"(bytes), "r"(mbar) : "memory");
}
#define MBAR_INIT(a, n) \
    asm volatile("mbarrier.init.shared.b64 [%0], %1;" :: "r"(a), "r"(n) : "memory")
#define MBAR_EXPECT(a, tx) \
    asm volatile("mbarrier.arrive.expect_tx.shared.b64 _, [%0], %1;" :: "r"(a), "r"(tx) : "memory")
#define MBAR_ARRIVE(a) \
    asm volatile("mbarrier.arrive.shared.b64 _, [%0];" :: "r"(a) : "memory")
__device__ __forceinline__ void mbar_wait(uint32_t mbar, uint32_t parity) {
    uint32_t done;
    asm volatile(
        "{\n\t.reg .pred p;\n\t"
        "mbarrier.try_wait.parity.acquire.cta.shared::cta.b64 p, [%1], %2;\n\t"
        "selp.b32 %0, 1, 0, p;\n\t}"
        : "=r"(done) : "r"(mbar), "r"(parity) : "memory");
    if (!done) {
        asm volatile(
            "{\n\t.reg .pred P1;\n\t"
            "WL_%=:\n\t"
            "mbarrier.try_wait.parity.acquire.cta.shared::cta.b64 P1, [%0], %1, 0x989680;\n\t"
            "@P1 bra.uni WD_%=;\n\t"
            "bra.uni WL_%=;\n\t"
            "WD_%=:\n\t}"
            :: "r"(mbar), "r"(parity) : "memory");
    }
}

// ---------------- prep: warp-per-row convert + K-tile + swizzle ----------
// 4 rows per 128-thread block; float4 loads; smem-staged bf16; 16B stores.
template <int NROWS, int ISCLIP>
__global__ void prep_kernel(const float* __restrict__ src) {
    __shared__ __nv_bfloat16 srow[4][DIM];
    const int lane = threadIdx.x & 31;
    const int w = threadIdx.x >> 5;
    const int r = blockIdx.x * 4 + w;
    const float* row = src + (size_t)r * DIM;

    float ss = 0.f;
    #pragma unroll
    for (int i = 0; i < 6; i++) {             // 6 float4 per lane = 24 elems
        int f4 = lane + i * 32;               // 192 float4 = 768 floats
        float4 x = *(const float4*)&row[f4 * 4];
        if (ISCLIP) ss += x.x * x.x + x.y * x.y + x.z * x.z + x.w * x.w;
        __nv_bfloat16* d = &srow[w][f4 * 4];
        d[0] = __float2bfloat16(x.x);
        d[1] = __float2bfloat16(x.y);
        d[2] = __float2bfloat16(x.z);
        d[3] = __float2bfloat16(x.w);
    }
    if (ISCLIP) {
        #pragma unroll
        for (int off = 16; off > 0; off >>= 1)
            ss += __shfl_xor_sync(0xffffffffu, ss, off);
        if (lane == 0) g_c_sq[r] = ss;
    }
    __syncwarp();
    uint8_t* gbase = ISCLIP ? g_clip_t : g_prompt_t;
    const size_t nrows = NROWS;
    #pragma unroll
    for (int t = 0; t < 3; t++) {             // 96 segs of 16B per row
        int seg = lane + t * 32;
        int c = seg >> 3, k = seg & 7;
        uint4 val = *(const uint4*)&srow[w][c * 64 + k * 8];
        uint8_t* dst = gbase + ((size_t)c * nrows + r) * 128
                     + ((k * 16) ^ ((r & 7) << 4));
        *(uint4*)dst = val;
    }
    if (!ISCLIP && lane == 0) {
        g_keys2[r] = 0xFFFFFFFFFFFFFFFFull;
        g_rowmin[r] = 0xFFFFFFFFu;            // +inf ordered key (monotone filter)
        if (r == 0) g_cand_count = 0u;
    }
}

// ---------------- Pass A: skew-pipelined bf16 GEMM + candidates ---------
__global__ void __launch_bounds__(256, 2)
nn_kernel() {
    extern __shared__ __align__(1024) char smem[];
    const uint32_t sb = smem_u32(smem);
    const int tid = threadIdx.x;
    const int wid = tid >> 5, lane = tid & 31;
    const int wm = wid & 1, wn = wid >> 1;
    const int g = lane >> 2, tid4 = lane & 3;
    const int j = lane & 7, sel = lane >> 3;
    const int p0 = blockIdx.x * BM;
    const int v0 = blockIdx.y * BN;
    const uint32_t mb_full  = sb + RM_OFF + 640;   // 3 x 8B
    const uint32_t mb_empty = sb + RM_OFF + 672;   // 3 x 8B

    if (tid == 0) {
        #pragma unroll
        for (int s = 0; s < 3; s++) {
            MBAR_INIT(mb_full + s * 8, 1u);
            MBAR_INIT(mb_empty + s * 8, 256u);
        }
    }
    __syncthreads();

    auto issue = [&](int c) {
        int s = c % 3;
        uint32_t stage = sb + s * STAGE_BYTES;
        MBAR_EXPECT(mb_full + s * 8, (uint32_t)STAGE_BYTES);
        bulk_g2s(stage, g_prompt_t + ((size_t)c * PROMPT_LEN + p0) * 128,
                 ASTAGE_BYTES, mb_full + s * 8);
        bulk_g2s(stage + ASTAGE_BYTES, g_clip_t + ((size_t)c * VOCAB + v0) * 128,
                 ASTAGE_BYTES, mb_full + s * 8);
    };

    if (tid == 0) { issue(0); issue(1); issue(2); }

    float acc[4][4][4];
    #pragma unroll
    for (int m = 0; m < 4; m++)
        #pragma unroll
        for (int n = 0; n < 4; n++)
            #pragma unroll
            for (int q = 0; q < 4; q++) acc[m][n][q] = 0.f;

    const uint32_t a_row = (uint32_t)(j + 8 * (sel & 1)) * 128u;
    const uint32_t b_row = (uint32_t)(j + 8 * (sel >> 1)) * 128u;
    const uint32_t a_c16 = 16u * (uint32_t)(sel >> 1);
    const uint32_t b_c16 = 16u * (uint32_t)(sel & 1);
    const uint32_t xorm = (uint32_t)j << 4;

    for (int c = 0; c < NCHUNK; c++) {
        const int s = c % 3;

        mbar_wait(mb_full + s * 8, (uint32_t)((c / 3) & 1));

        const uint32_t stA = sb + (uint32_t)s * STAGE_BYTES;
        const uint32_t stB = stA + ASTAGE_BYTES;
        #pragma unroll
        for (int ks = 0; ks < 4; ks++) {       // 4 x k16 = 64 bf16 = 32B steps
            const uint32_t KB = (uint32_t)ks * 32u;
            uint32_t a[4][4], b[2][4];
            #pragma unroll
            for (int mf = 0; mf < 4; mf++) {
                uint32_t addr = stA + (uint32_t)(wm * 64 + mf * 16) * 128u + a_row
                              + ((KB + a_c16) ^ xorm);
                ldsm4(a[mf], addr);
            }
            #pragma unroll
            for (int nf2 = 0; nf2 < 2; nf2++) {
                uint32_t addr = stB + (uint32_t)(wn * 32 + nf2 * 16) * 128u + b_row
                              + ((KB + b_c16) ^ xorm);
                ldsm4(b[nf2], addr);
            }
            #pragma unroll
            for (int mf = 0; mf < 4; mf++)
                #pragma unroll
                for (int nf = 0; nf < 4; nf++)
                    mma16816(acc[mf][nf], a[mf], b[nf >> 1][2 * (nf & 1)],
                             b[nf >> 1][2 * (nf & 1) + 1]);
        }
        // this thread is done reading stage s for round c/3
        MBAR_ARRIVE(mb_empty + s * 8);

        // producer refills AFTER its own arrive (R11 deadlock lesson)
        if (tid == 0 && c + 3 < NCHUNK) {
            mbar_wait(mb_empty + s * 8, (uint32_t)((c / 3) & 1));
            issue(c + 3);
        }
    }

    // ---------------- epilogue ----------------
    unsigned* rowmin = (unsigned*)(smem + RM_OFF);
    unsigned* s_cnt  = (unsigned*)(smem + RM_OFF + 512);
    unsigned* s_base = (unsigned*)(smem + RM_OFF + 516);
    float* gthr      = (float*)(smem + RM_OFF + 1024);   // 128 floats
    float4* staging  = (float4*)smem;

    if (tid < BM) rowmin[tid] = 0xFFFFFFFFu;
    if (tid == 0) *s_cnt = 0u;
    __syncthreads();     // all warps out of mainloop; staging smem free

    float cs[8];
    #pragma unroll
    for (int nf = 0; nf < 4; nf++)
        #pragma unroll
        for (int jj = 0; jj < 2; jj++)
            cs[nf * 2 + jj] = __ldg(&g_c_sq[v0 + wn * 32 + nf * 8 + 2 * tid4 + jj]);

    // CTA per-row min (quad-reduced)
    #pragma unroll
    for (int mf = 0; mf < 4; mf++)
        #pragma unroll
        for (int h = 0; h < 2; h++) {
            int lr = wm * 64 + mf * 16 + h * 8 + g;
            float best = 3.4e38f;
            #pragma unroll
            for (int nf = 0; nf < 4; nf++)
                #pragma unroll
                for (int jj = 0; jj < 2; jj++) {
                    float s = cs[nf * 2 + jj] - 2.0f * acc[mf][nf][h * 2 + jj];
                    best = fminf(best, s);
                }
            #pragma unroll
            for (int off = 1; off < 4; off <<= 1)
                best = fminf(best, __shfl_xor_sync(0xffffffffu, best, off));
            if (tid4 == 0) atomicMin(&rowmin[lr], f2ord(best));
        }
    __syncthreads();

    // publish CTA mins (monotone tightening) + read current global bound.
    // Stale (larger) reads only loosen the filter -> still a superset of the
    // candidates the exact rescore needs. reduce_min recomputes exact later.
    if (tid < BM) {
        atomicMin(&g_rowmin[p0 + tid], rowmin[tid]);
        gthr[tid] = ord2f(__ldg(&g_rowmin[p0 + tid]));
    }
    __syncthreads();

    // warp-aggregated candidate push (CTA-local AND global-so-far filter)
    #pragma unroll
    for (int mf = 0; mf < 4; mf++)
        #pragma unroll
        for (int h = 0; h < 2; h++) {
            int lr = wm * 64 + mf * 16 + h * 8 + g;
            float thr = fminf(ord2f(rowmin[lr]), gthr[lr]) + EPS;
            #pragma unroll
            for (int nf = 0; nf < 4; nf++)
                #pragma unroll
                for (int jj = 0; jj < 2; jj++) {
                    float s = cs[nf * 2 + jj] - 2.0f * acc[mf][nf][h * 2 + jj];
                    bool pred = (s <= thr);
                    unsigned mask = __ballot_sync(0xffffffffu, pred);
                    if (mask) {
                        int leader = __ffs(mask) - 1;
                        unsigned base = 0;
                        if (lane == leader)
                            base = atomicAdd(s_cnt, (unsigned)__popc(mask));
                        base = __shfl_sync(0xffffffffu, base, leader);
                        if (pred) {
                            unsigned slot = base + __popc(mask & ((1u << lane) - 1u));
                            float4 val = make_float4(
                                s, __uint_as_float((unsigned)(p0 + lr)),
                                __uint_as_float((unsigned)(v0 + wn * 32 + nf * 8 + 2 * tid4 + jj)),
                                0.f);
                            if (slot < STAGE_CAP) staging[slot] = val;
                            else {
                                unsigned gs = atomicAdd(&g_cand_count, 1u);
                                if (gs < CAND_CAP) g_cand[gs] = val;
                            }
                        }
                    }
                }
        }
    __syncthreads();
    unsigned cnt = min(*s_cnt, STAGE_CAP);
    if (tid == 0) *s_base = atomicAdd(&g_cand_count, cnt);
    if (tid < BM)
        g_ctamin[(size_t)blockIdx.y * PROMPT_LEN + p0 + tid] = rowmin[tid];
    __syncthreads();
    unsigned base = *s_base;
    for (unsigned i = tid; i < cnt; i += 256)
        if (base + i < CAND_CAP) g_cand[base + i] = staging[i];
}

// ---------------- global row-min reduce (exact) ----------------
__global__ void reduce_min_kernel() {
    int r = blockIdx.x;
    unsigned m = 0xFFFFFFFFu;
    for (int v = threadIdx.x; v < NVT; v += 128)
        m = min(m, g_ctamin[(size_t)v * PROMPT_LEN + r]);
    #pragma unroll
    for (int off = 16; off > 0; off >>= 1)
        m = min(m, __shfl_xor_sync(0xffffffffu, m, off));
    __shared__ unsigned wmin[4];
    if ((threadIdx.x & 31) == 0) wmin[threadIdx.x >> 5] = m;
    __syncthreads();
    if (threadIdx.x == 0) {
        m = min(min(wmin[0], wmin[1]), min(wmin[2], wmin[3]));
        g_rowmin[r] = m;
    }
}

// ---------------- Pass B: exact rescore ----------------
__global__ void rescore_kernel(const float* __restrict__ prompt,
                               const float* __restrict__ clip) {
    unsigned n = g_cand_count;
    if (n > CAND_CAP) n = CAND_CAP;
    int lane = threadIdx.x & 31;
    unsigned gw = (blockIdx.x * blockDim.x + threadIdx.x) >> 5;
    unsigned nw = (gridDim.x * blockDim.x) >> 5;
    for (unsigned i = gw; i < n; i += nw) {
        float4 cand = g_cand[i];
        float s = cand.x;
        unsigned row = __float_as_uint(cand.y);
        unsigned col = __float_as_uint(cand.z);
        float minf = ord2f(g_rowmin[row]);
        if (s <= minf + EPS) {
            const float* p = prompt + (size_t)row * DIM;
            const float* c = clip + (size_t)col * DIM;
            double d2 = 0.0;
            for (int k = lane; k < DIM; k += 32) {
                double d = (double)p[k] - (double)c[k];
                d2 += d * d;
            }
            #pragma unroll
            for (int off = 16; off > 0; off >>= 1)
                d2 += __shfl_xor_sync(0xffffffffu, d2, off);
            if (lane == 0) {
                unsigned long long q = (unsigned long long)llround(d2 * 1048576.0);
                atomicMin(&g_keys2[row], (q << 16) | (unsigned long long)col);
            }
        }
    }
}

// ---------------- gather ----------------
__global__ void gather_kernel(const float* __restrict__ clip,
                              float* __restrict__ out, int write_ids) {
    int p = blockIdx.x;
    unsigned idx = (unsigned)(g_keys2[p] & 0xFFFFull);
    const float* src = clip + (size_t)idx * DIM;
    float* dst = out + (size_t)p * DIM;
    for (int i = threadIdx.x; i < DIM; i += blockDim.x) dst[i] = src[i];
    if (threadIdx.x == 0 && write_ids)
        out[(size_t)PROMPT_LEN * DIM + p] = (float)idx;
}

// ---------------- launch ----------------
extern "C" void kernel_launch(void* const* d_in, const int* in_sizes, int n_in,
                              void* d_out, int out_size) {
    const float* prompt = (const float*)d_in[0];   // (2048, 768) fp32
    const float* clip   = (const float*)d_in[1];   // (49408, 768) fp32
    float* out = (float*)d_out;

    cudaFuncSetAttribute(nn_kernel, cudaFuncAttributeMaxDynamicSharedMemorySize,
                         SMEM_TOTAL);

    prep_kernel<VOCAB, 1><<<VOCAB / 4, 128>>>(clip);
    prep_kernel<PROMPT_LEN, 0><<<PROMPT_LEN / 4, 128>>>(prompt);

    dim3 grid(PROMPT_LEN / BM, NVT);   // (16, 386); x fast -> clip tile reuse in L2
    nn_kernel<<<grid, 256, SMEM_TOTAL>>>();

    reduce_min_kernel<<<PROMPT_LEN, 128>>>();
    rescore_kernel<<<512, 256>>>(prompt, clip);

    int write_ids = (out_size >= PROMPT_LEN * DIM + PROMPT_LEN) ? 1 : 0;
    gather_kernel<<<PROMPT_LEN, 128>>>(clip, out, write_ids);
}